// round 2
// baseline (speedup 1.0000x reference)
#include <cuda_runtime.h>
#include <cuda_bf16.h>

#define HH 512
#define WW 512
#define TILE_W 64      // output cols per block (2 per thread.x)
#define TILE_H 64      // output rows per block (8 per thread.y)
#define RPT 8
#define SM_W 68        // pitch: 66 used cols (halo+64+halo), padded to keep float2 alignment
#define SM_H 66

#define C1f 0.0001f    // 0.01^2
#define C2f 0.0009f    // 0.03^2

__global__ __launch_bounds__(256)
void ssim_kernel(const float* __restrict__ x,
                 const float* __restrict__ y,
                 float* __restrict__ out)
{
    __shared__ float sx[SM_H][SM_W];
    __shared__ float sy[SM_H][SM_W];

    const int tx = threadIdx.x;              // 0..31 -> column pair within tile
    const int ty = threadIdx.y;              // 0..7  -> row strip
    const int tileX = blockIdx.x * TILE_W;
    const int tileY = blockIdx.y * TILE_H;
    const long plane_off = (long)blockIdx.z * (HH * WW);

    const float* xp = x + plane_off;
    const float* yp = y + plane_off;
    float* op = out + plane_off;

    // ---- cooperative load: smem local col l corresponds to global col tileX-1+l, l in [0,66) ----
    #pragma unroll
    for (int lr = ty; lr < SM_H; lr += 8) {
        const int gr = tileY - 1 + lr;
        const bool rok = (gr >= 0) && (gr < HH);
        const long rowb = (long)gr * WW;
        #pragma unroll
        for (int s = 0; s < 2; s++) {
            const int l = tx + 32 * s;
            const int gc = tileX - 1 + l;
            const bool ok = rok && (gc >= 0) && (gc < WW);
            sx[lr][l] = ok ? __ldg(xp + rowb + gc) : 0.0f;
            sy[lr][l] = ok ? __ldg(yp + rowb + gc) : 0.0f;
        }
        if (tx < 2) {
            const int l = 64 + tx;
            const int gc = tileX - 1 + l;          // left edge impossible here
            const bool ok = rok && (gc < WW);
            sx[lr][l] = ok ? __ldg(xp + rowb + gc) : 0.0f;
            sy[lr][l] = ok ? __ldg(yp + rowb + gc) : 0.0f;
        }
    }
    __syncthreads();

    // ---- each thread: output cols c0 = tileX+2*tx, c1 = c0+1; rows rbase..rbase+7 ----
    const int c0 = tileX + 2 * tx;
    const float invw0 = (c0 == 0) ? 0.5f : (1.0f / 3.0f);
    const float invw1 = (c0 + 1 == WW - 1) ? 0.5f : (1.0f / 3.0f);
    const int rbase = ty * RPT;

    // ring buffers: .x = col0, .y = col1
    float2 Hx[3], Hy[3], Hxx[3], Hyy[3], Hxy[3];

    // horizontal stage for smem row r -> slot k
    #define HROW(r, k)                                                          \
    {                                                                           \
        const float2 a = *(const float2*)&sx[(r)][2 * tx];                      \
        const float2 b = *(const float2*)&sx[(r)][2 * tx + 2];                  \
        const float2 p = *(const float2*)&sy[(r)][2 * tx];                      \
        const float2 q = *(const float2*)&sy[(r)][2 * tx + 2];                  \
        const float mx  = a.y + b.x;                                            \
        const float my  = p.y + q.x;                                            \
        const float mxx = fmaf(a.y, a.y, b.x * b.x);                            \
        const float myy = fmaf(p.y, p.y, q.x * q.x);                            \
        const float mxy = fmaf(a.y, p.y, b.x * q.x);                            \
        Hx[k]  = make_float2(a.x + mx,                 mx + b.y);               \
        Hy[k]  = make_float2(p.x + my,                 my + q.y);               \
        Hxx[k] = make_float2(fmaf(a.x, a.x, mxx),      fmaf(b.y, b.y, mxx));    \
        Hyy[k] = make_float2(fmaf(p.x, p.x, myy),      fmaf(q.y, q.y, myy));    \
        Hxy[k] = make_float2(fmaf(a.x, p.x, mxy),      fmaf(b.y, q.y, mxy));    \
    }

    HROW(rbase + 0, 0)
    HROW(rbase + 1, 1)

    #pragma unroll
    for (int i = 0; i < RPT; i++) {
        const int s = (i + 2) % 3;           // compile-time after unroll
        HROW(rbase + i + 2, s)

        const float2 Sx  = make_float2(Hx[0].x + Hx[1].x + Hx[2].x,
                                       Hx[0].y + Hx[1].y + Hx[2].y);
        const float2 Sy  = make_float2(Hy[0].x + Hy[1].x + Hy[2].x,
                                       Hy[0].y + Hy[1].y + Hy[2].y);
        const float2 Sxx = make_float2(Hxx[0].x + Hxx[1].x + Hxx[2].x,
                                       Hxx[0].y + Hxx[1].y + Hxx[2].y);
        const float2 Syy = make_float2(Hyy[0].x + Hyy[1].x + Hyy[2].x,
                                       Hyy[0].y + Hyy[1].y + Hyy[2].y);
        const float2 Sxy = make_float2(Hxy[0].x + Hxy[1].x + Hxy[2].x,
                                       Hxy[0].y + Hxy[1].y + Hxy[2].y);

        const int gr = tileY + rbase + i;
        const float invh = (gr == 0 || gr == HH - 1) ? 0.5f : (1.0f / 3.0f);
        const float inv0 = invw0 * invh;
        const float inv1 = invw1 * invh;

        float2 res;
        {
            const float mux = Sx.x * inv0, muy = Sy.x * inv0;
            const float vx  = fmaf(Sxx.x, inv0, -mux * mux);
            const float vy  = fmaf(Syy.x, inv0, -muy * muy);
            const float vxy = fmaf(Sxy.x, inv0, -mux * muy);
            const float num = fmaf(2.0f * mux, muy, C1f) * fmaf(2.0f, vxy, C2f);
            const float den = (fmaf(mux, mux, muy * muy) + C1f) * (vx + vy + C2f);
            const float ssim = __fdividef(num, den + 1e-12f);
            res.x = fminf(fmaxf(fmaf(-0.5f, ssim, 0.5f), 0.0f), 1.0f);
        }
        {
            const float mux = Sx.y * inv1, muy = Sy.y * inv1;
            const float vx  = fmaf(Sxx.y, inv1, -mux * mux);
            const float vy  = fmaf(Syy.y, inv1, -muy * muy);
            const float vxy = fmaf(Sxy.y, inv1, -mux * muy);
            const float num = fmaf(2.0f * mux, muy, C1f) * fmaf(2.0f, vxy, C2f);
            const float den = (fmaf(mux, mux, muy * muy) + C1f) * (vx + vy + C2f);
            const float ssim = __fdividef(num, den + 1e-12f);
            res.y = fminf(fmaxf(fmaf(-0.5f, ssim, 0.5f), 0.0f), 1.0f);
        }

        *(float2*)(op + (long)gr * WW + c0) = res;
    }
    #undef HROW
}

extern "C" void kernel_launch(void* const* d_in, const int* in_sizes, int n_in,
                              void* d_out, int out_size)
{
    const float* x = (const float*)d_in[0];
    const float* y = (const float*)d_in[1];
    float* out = (float*)d_out;

    const int planes = out_size / (HH * WW);   // 16*3 = 48
    dim3 block(32, 8);
    dim3 grid(WW / TILE_W, HH / TILE_H, planes);
    ssim_kernel<<<grid, block>>>(x, y, out);
}

// round 8
// speedup vs baseline: 1.2170x; 1.2170x over previous
#include <cuda_runtime.h>
#include <cuda_bf16.h>

#define HH 512
#define WW 512
#define TILE_W 64      // output cols per block (2 per thread.x)
#define TILE_H 64      // output rows per block (8 per thread.y)
#define RPT 8
#define SM_W 68        // pitch: 66 used cols (halo+64+halo), padded for float2 alignment
#define SM_H 66

#define C1f 0.0001f    // 0.01^2
#define C2f 0.0009f    // 0.03^2

__global__ __launch_bounds__(256, 5)
void ssim_kernel(const float* __restrict__ x,
                 const float* __restrict__ y,
                 float* __restrict__ out)
{
    __shared__ float sx[SM_H][SM_W];
    __shared__ float sy[SM_H][SM_W];

    const int tx = threadIdx.x;              // 0..31 -> column pair within tile
    const int ty = threadIdx.y;              // 0..7  -> row strip
    const int tileX = blockIdx.x * TILE_W;
    const int tileY = blockIdx.y * TILE_H;
    const int plane_off = blockIdx.z * (HH * WW);   // fits in int (48*262144)

    const float* xp = x + plane_off;
    const float* yp = y + plane_off;
    float* op = out + plane_off;

    // ---- cooperative load: smem col l == global col tileX-1+l, l in [0,66) ----
    const bool interior = (tileX != 0) & (tileX + TILE_W != WW) &
                          (tileY != 0) & (tileY + TILE_H != HH);
    if (interior) {
        // no boundary checks: rows tileY-1..tileY+64, cols tileX-1..tileX+64 all valid
        #pragma unroll
        for (int lr = ty; lr < SM_H; lr += 8) {
            const int base = (tileY - 1 + lr) * WW + tileX - 1;
            sx[lr][tx]      = __ldg(xp + base + tx);
            sx[lr][tx + 32] = __ldg(xp + base + tx + 32);
            sy[lr][tx]      = __ldg(yp + base + tx);
            sy[lr][tx + 32] = __ldg(yp + base + tx + 32);
            if (tx < 2) {
                sx[lr][64 + tx] = __ldg(xp + base + 64 + tx);
                sy[lr][64 + tx] = __ldg(yp + base + 64 + tx);
            }
        }
    } else {
        #pragma unroll
        for (int lr = ty; lr < SM_H; lr += 8) {
            const int gr = tileY - 1 + lr;
            const bool rok = (gr >= 0) && (gr < HH);
            const int rowb = gr * WW;
            #pragma unroll
            for (int s = 0; s < 2; s++) {
                const int l = tx + 32 * s;
                const int gc = tileX - 1 + l;
                const bool ok = rok && (gc >= 0) && (gc < WW);
                sx[lr][l] = ok ? __ldg(xp + rowb + gc) : 0.0f;
                sy[lr][l] = ok ? __ldg(yp + rowb + gc) : 0.0f;
            }
            if (tx < 2) {
                const int l = 64 + tx;
                const int gc = tileX - 1 + l;      // left edge impossible here
                const bool ok = rok && (gc < WW);
                sx[lr][l] = ok ? __ldg(xp + rowb + gc) : 0.0f;
                sy[lr][l] = ok ? __ldg(yp + rowb + gc) : 0.0f;
            }
        }
    }
    __syncthreads();

    // ---- each thread: output cols c0 = tileX+2*tx, c1 = c0+1; rows rbase..rbase+7 ----
    const int c0 = tileX + 2 * tx;
    const float invw0 = (c0 == 0) ? 0.5f : (1.0f / 3.0f);
    const float invw1 = (c0 + 1 == WW - 1) ? 0.5f : (1.0f / 3.0f);
    const int rbase = ty * RPT;

    // ring buffers: .x = col0, .y = col1
    float2 Hx[3], Hy[3], Hxx[3], Hyy[3], Hxy[3];

    // horizontal stage for smem row r -> slot k (aligned LDS.64 pairs)
    #define HROW(r, k)                                                          \
    {                                                                           \
        const float2 a = *(const float2*)&sx[(r)][2 * tx];                      \
        const float2 b = *(const float2*)&sx[(r)][2 * tx + 2];                  \
        const float2 p = *(const float2*)&sy[(r)][2 * tx];                      \
        const float2 q = *(const float2*)&sy[(r)][2 * tx + 2];                  \
        const float mx  = a.y + b.x;                                            \
        const float my  = p.y + q.x;                                            \
        const float mxx = fmaf(a.y, a.y, b.x * b.x);                            \
        const float myy = fmaf(p.y, p.y, q.x * q.x);                            \
        const float mxy = fmaf(a.y, p.y, b.x * q.x);                            \
        Hx[k]  = make_float2(a.x + mx,                 mx + b.y);               \
        Hy[k]  = make_float2(p.x + my,                 my + q.y);               \
        Hxx[k] = make_float2(fmaf(a.x, a.x, mxx),      fmaf(b.y, b.y, mxx));    \
        Hyy[k] = make_float2(fmaf(p.x, p.x, myy),      fmaf(q.y, q.y, myy));    \
        Hxy[k] = make_float2(fmaf(a.x, p.x, mxy),      fmaf(b.y, q.y, mxy));    \
    }

    HROW(rbase + 0, 0)
    HROW(rbase + 1, 1)

    #pragma unroll
    for (int i = 0; i < RPT; i++) {
        const int s = (i + 2) % 3;           // compile-time after unroll
        HROW(rbase + i + 2, s)

        const float2 Sx  = make_float2(Hx[0].x + Hx[1].x + Hx[2].x,
                                       Hx[0].y + Hx[1].y + Hx[2].y);
        const float2 Sy  = make_float2(Hy[0].x + Hy[1].x + Hy[2].x,
                                       Hy[0].y + Hy[1].y + Hy[2].y);
        const float2 Sxx = make_float2(Hxx[0].x + Hxx[1].x + Hxx[2].x,
                                       Hxx[0].y + Hxx[1].y + Hxx[2].y);
        const float2 Syy = make_float2(Hyy[0].x + Hyy[1].x + Hyy[2].x,
                                       Hyy[0].y + Hyy[1].y + Hyy[2].y);
        const float2 Sxy = make_float2(Hxy[0].x + Hxy[1].x + Hxy[2].x,
                                       Hxy[0].y + Hxy[1].y + Hxy[2].y);

        const int gr = tileY + rbase + i;
        const float invh = (gr == 0 || gr == HH - 1) ? 0.5f : (1.0f / 3.0f);
        const float inv0 = invw0 * invh;
        const float inv1 = invw1 * invh;

        float2 res;
        {
            const float mux = Sx.x * inv0, muy = Sy.x * inv0;
            const float vx  = fmaf(Sxx.x, inv0, -mux * mux);
            const float vy  = fmaf(Syy.x, inv0, -muy * muy);
            const float vxy = fmaf(Sxy.x, inv0, -mux * muy);
            const float num = fmaf(2.0f * mux, muy, C1f) * fmaf(2.0f, vxy, C2f);
            const float den = (fmaf(mux, mux, muy * muy) + C1f) * (vx + vy + C2f);
            const float ssim = __fdividef(num, den + 1e-12f);
            res.x = fminf(fmaxf(fmaf(-0.5f, ssim, 0.5f), 0.0f), 1.0f);
        }
        {
            const float mux = Sx.y * inv1, muy = Sy.y * inv1;
            const float vx  = fmaf(Sxx.y, inv1, -mux * mux);
            const float vy  = fmaf(Syy.y, inv1, -muy * muy);
            const float vxy = fmaf(Sxy.y, inv1, -mux * muy);
            const float num = fmaf(2.0f * mux, muy, C1f) * fmaf(2.0f, vxy, C2f);
            const float den = (fmaf(mux, mux, muy * muy) + C1f) * (vx + vy + C2f);
            const float ssim = __fdividef(num, den + 1e-12f);
            res.y = fminf(fmaxf(fmaf(-0.5f, ssim, 0.5f), 0.0f), 1.0f);
        }

        // streaming store: output is write-once, keep it out of L2's way
        __stcs((float2*)(op + gr * WW + c0), res);
    }
    #undef HROW
}

extern "C" void kernel_launch(void* const* d_in, const int* in_sizes, int n_in,
                              void* d_out, int out_size)
{
    const float* x = (const float*)d_in[0];
    const float* y = (const float*)d_in[1];
    float* out = (float*)d_out;

    const int planes = out_size / (HH * WW);   // 16*3 = 48
    dim3 block(32, 8);
    dim3 grid(WW / TILE_W, HH / TILE_H, planes);
    ssim_kernel<<<grid, block>>>(x, y, out);
}